// round 15
// baseline (speedup 1.0000x reference)
#include <cuda_runtime.h>
#include <cuda_bf16.h>
#include <stdint.h>

// Problem constants
#define BB 4
#define XX 32
#define HH 8
#define WW 128
#define CC 32
#define NQ 128          // distinct query rows per batch
#define MM 4096         // key rows per batch
#define DD 256          // reduction dim

// Packed bf16x2 (low 16 = hi part, high 16 = lo part) stored in float arrays.
__device__ __align__(16) float g_Qp [BB*NQ*DD];    // [b][n][cc]
__device__ __align__(16) float g_Kp [BB*MM*DD];    // [b][m][cc]
__device__ __align__(16) float g_Vp [BB*MM*DD];    // [b][m][cc]
__device__ __align__(16) float g_Vtp[BB*DD*MM];    // [b][cc][m]
__device__ __align__(16) float g_O  [BB*NQ*DD];    // fp32 accum
__device__ __align__(16) float g_rowsum[BB*NQ];
__device__ __align__(16) float g_W1[96*72];        // conv weights dual-hi (wh,wh)
__device__ __align__(16) float g_W2[96*72];        // conv weights dual-lo (wl,wl)

// ---------------------------------------------------------------------------
// helpers
// ---------------------------------------------------------------------------
__device__ __forceinline__ float pack_bf(float v) {
    __nv_bfloat16 h = __float2bfloat16(v);
    __nv_bfloat16 l = __float2bfloat16(v - __bfloat162float(h));
    uint32_t w = ((uint32_t)__bfloat16_as_ushort(l) << 16) |
                 (uint32_t)__bfloat16_as_ushort(h);
    return __uint_as_float(w);
}
__device__ __forceinline__ uint32_t prmt_rep(uint32_t a, uint32_t sel) {
    uint32_t d;
    asm("prmt.b32 %0, %1, %2, %3;" : "=r"(d) : "r"(a), "r"(0u), "r"(sel));
    return d;
}
__device__ __forceinline__ void mma16(float4& d, const uint32_t* a,
                                      uint32_t b0, uint32_t b1) {
    asm volatile(
        "mma.sync.aligned.m16n8k16.row.col.f32.bf16.bf16.f32 "
        "{%0,%1,%2,%3},{%4,%5,%6,%7},{%8,%9},{%0,%1,%2,%3};"
        : "+f"(d.x), "+f"(d.y), "+f"(d.z), "+f"(d.w)
        : "r"(a[0]), "r"(a[1]), "r"(a[2]), "r"(a[3]), "r"(b0), "r"(b1));
}
__device__ __forceinline__ uint32_t smaddr(const void* p) {
    return (uint32_t)__cvta_generic_to_shared(p);
}
__device__ __forceinline__ void ldsm4(uint32_t r[4], const float* p) {
    uint32_t a = smaddr(p);
    asm volatile("ldmatrix.sync.aligned.m8n8.x4.shared.b16 {%0,%1,%2,%3}, [%4];"
                 : "=r"(r[0]), "=r"(r[1]), "=r"(r[2]), "=r"(r[3]) : "r"(a));
}
__device__ __forceinline__ void ldsm2(uint32_t r[2], const float* p) {
    uint32_t a = smaddr(p);
    asm volatile("ldmatrix.sync.aligned.m8n8.x2.shared.b16 {%0,%1}, [%2];"
                 : "=r"(r[0]), "=r"(r[1]) : "r"(a));
}
#define CPA(dst, src) asm volatile("cp.async.cg.shared.global [%0], [%1], 16;" \
                                   :: "r"(dst), "l"(src))
#define CP_COMMIT() asm volatile("cp.async.commit_group;")

// ---------------------------------------------------------------------------
// Kernel 1: Q projection -> packed bf16x2; zero g_O/g_rowsum; conv weights
// expanded into dual-replicated bf16x2 (W1=(wh,wh), W2=(wl,wl)).
// ---------------------------------------------------------------------------
__global__ __launch_bounds__(256) void k_q(const float* __restrict__ target,
                                           const float* __restrict__ w_q,
                                           const float* __restrict__ b_q,
                                           const float* __restrict__ w_cross) {
    int t = blockIdx.x * 256 + threadIdx.x;       // [0, 131072)
    g_O[t] = 0.f;
    if (t < BB*NQ) g_rowsum[t] = 0.f;
    if (t < 96*72) {
        int k = t / 72, o = t - k*72;
        float v = (o < 64) ? w_cross[(o*32 + (k & 31))*3 + (k >> 5)] : 0.f;
        __nv_bfloat16 h = __float2bfloat16(v);
        __nv_bfloat16 l = __float2bfloat16(v - __bfloat162float(h));
        uint32_t hu = __bfloat16_as_ushort(h), lu = __bfloat16_as_ushort(l);
        g_W1[t] = __uint_as_float((hu << 16) | hu);
        g_W2[t] = __uint_as_float((lu << 16) | lu);
    }

    int b   = t >> 15;
    int n   = (t >> 8) & 127;
    int cc  = t & 255;
    int o   = n >> 2, whi = n & 3;
    int wlo = cc >> 3, h = cc & 7;
    int w   = whi * 32 + wlo;
    const float4* trow = (const float4*)(target + ((b*HH + h)*WW + w)*CC);
    const float4* wrow = (const float4*)(w_q + o*CC);
    float acc = b_q[o];
#pragma unroll
    for (int i = 0; i < 8; i++) {
        float4 a = trow[i], ww = wrow[i];
        acc += a.x*ww.x + a.y*ww.y + a.z*ww.z + a.w*ww.w;
    }
    g_Qp[t] = pack_bf(acc);
}

// ---------------------------------------------------------------------------
// Kernel 2: conv3d (3,1,1) im2col GEMM, double-bf16, dependency-pipelined.
// ---------------------------------------------------------------------------
#define CONV_SMEM_FLOATS (18*264 + 2*96*72 + 64)
__global__ __launch_bounds__(256, 2) void k_conv(const float* __restrict__ storage,
                                                 const float* __restrict__ b_cross) {
    extern __shared__ float sm[];
    float* Ss  = sm;                    // 18*264 packed slab
    float* W1  = Ss + 18*264;           // 96*72 dual-hi
    float* W2  = W1 + 96*72;            // 96*72 dual-lo
    float* bsh = W2 + 96*72;            // 64

    int tid  = threadIdx.x;
    int bidx = blockIdx.x;              // b*256 + w*2 + xh
    int b  = bidx >> 8;
    int w  = (bidx >> 1) & 127;
    int xh = bidx & 1;
    int x0 = xh * 16;

    {
        const float4* s1 = (const float4*)g_W1;
        const float4* s2 = (const float4*)g_W2;
        float4* d1 = (float4*)W1;
        float4* d2 = (float4*)W2;
        for (int i = tid; i < 1728; i += 256) { d1[i] = s1[i]; d2[i] = s2[i]; }
    }
    if (tid < 64) bsh[tid] = b_cross[tid];

    for (int i = tid; i < 18*64; i += 256) {
        int si = i >> 6, r = i & 63;
        int c4 = (r & 7)*4, h = r >> 3;
        int xx = x0 - 1 + si;
        float4 v = make_float4(0.f, 0.f, 0.f, 0.f);
        if (xx >= 0 && xx < XX)
            v = *(const float4*)(storage + (((b*XX + xx)*HH + h)*WW + w)*CC + c4);
        float* ps = Ss + si*264 + c4*8 + h;
        ps[0]  = pack_bf(v.x);
        ps[8]  = pack_bf(v.y);
        ps[16] = pack_bf(v.z);
        ps[24] = pack_bf(v.w);
    }
    __syncthreads();

    int lane = tid & 31, ww = tid >> 5;
    int lr = lane >> 2, lc = lane & 3;
    int wm = ww & 3, wn = ww >> 2;      // 4m x 2n warps; warp tile 32x32
    float4 acc[2][4];
#pragma unroll
    for (int i = 0; i < 2; i++)
#pragma unroll
        for (int j = 0; j < 4; j++) acc[i][j] = make_float4(0.f,0.f,0.f,0.f);

#pragma unroll
    for (int ksl = 0; ksl < 12; ksl++) {
        int k0 = ksl*8;
        int dx = k0 >> 5, cib = k0 & 31;
        uint32_t ar[2][4];
#pragma unroll
        for (int mt = 0; mt < 2; mt++) {
            int rowb = wm*32 + mt*16;
            int xl = rowb >> 3;
            const float* p = Ss + (xl + dx)*264 + (cib + lc)*8 + lr;
            ar[mt][0] = __float_as_uint(p[0]);
            ar[mt][1] = __float_as_uint(p[264]);
            ar[mt][2] = __float_as_uint(p[32]);
            ar[mt][3] = __float_as_uint(p[264+32]);
        }
        uint32_t bh[4][2], bL[4][2];
#pragma unroll
        for (int nt = 0; nt < 4; nt++) {
            int nb = wn*32 + nt*8;
            bh[nt][0] = __float_as_uint(W1[(k0 + lc)*72 + nb + lr]);
            bh[nt][1] = __float_as_uint(W1[(k0 + lc + 4)*72 + nb + lr]);
            bL[nt][0] = __float_as_uint(W2[(k0 + lc)*72 + nb + lr]);
            bL[nt][1] = __float_as_uint(W2[(k0 + lc + 4)*72 + nb + lr]);
        }
#pragma unroll
        for (int nt = 0; nt < 4; nt++)
#pragma unroll
            for (int mt = 0; mt < 2; mt++)
                mma16(acc[mt][nt], ar[mt], bh[nt][0], bh[nt][1]);
#pragma unroll
        for (int nt = 0; nt < 4; nt++)
#pragma unroll
            for (int mt = 0; mt < 2; mt++)
                mma16(acc[mt][nt], ar[mt], bL[nt][0], bL[nt][1]);
    }

    int wb = w >> 5, ccb = (w & 31)*8;
#pragma unroll
    for (int mt = 0; mt < 2; mt++) {
        int rowb = wm*32 + mt*16;
        int x = x0 + (rowb >> 3);
        int h = lr;
#pragma unroll
        for (int nt = 0; nt < 4; nt++) {
            int o0 = wn*32 + nt*8 + lc*2;
            float4 d = acc[mt][nt];
            {
                float v0 = d.x + bsh[o0], v1 = d.y + bsh[o0+1];
                float* d0 = (o0     < 32) ? g_Vp : g_Kp;
                float* d1 = (o0 + 1 < 32) ? g_Vp : g_Kp;
                d0[(b*MM + (o0&31)*128     + x*4 + wb)*DD + ccb + h] = pack_bf(v0);
                d1[(b*MM + ((o0+1)&31)*128 + x*4 + wb)*DD + ccb + h] = pack_bf(v1);
            }
            {
                float v0 = d.z + bsh[o0], v1 = d.w + bsh[o0+1];
                float* d0 = (o0     < 32) ? g_Vp : g_Kp;
                float* d1 = (o0 + 1 < 32) ? g_Vp : g_Kp;
                d0[(b*MM + (o0&31)*128     + (x+1)*4 + wb)*DD + ccb + h] = pack_bf(v0);
                d1[(b*MM + ((o0+1)&31)*128 + (x+1)*4 + wb)*DD + ccb + h] = pack_bf(v1);
            }
        }
    }
}

// ---------------------------------------------------------------------------
// Kernel 3: V transpose (packed words)  [b][m][cc] -> [b][cc][m].
// ---------------------------------------------------------------------------
__global__ __launch_bounds__(256) void k_vt() {
    __shared__ float ts[64*65];
    int tid = threadIdx.x;
    int b  = blockIdx.x >> 8;
    int mt = (blockIdx.x >> 2) & 63;
    int ct = blockIdx.x & 3;
#pragma unroll
    for (int it = 0; it < 4; it++) {
        int i = tid + it*256;
        int r = i >> 4, c4 = (i & 15)*4;
        float4 v = *(const float4*)(g_Vp + (b*MM + mt*64 + r)*DD + ct*64 + c4);
        ts[r*65 + c4 + 0] = v.x; ts[r*65 + c4 + 1] = v.y;
        ts[r*65 + c4 + 2] = v.z; ts[r*65 + c4 + 3] = v.w;
    }
    __syncthreads();
#pragma unroll
    for (int it = 0; it < 4; it++) {
        int i = tid + it*256;
        int c = i >> 4, r4 = (i & 15)*4;
        float4 o = make_float4(ts[(r4+0)*65 + c], ts[(r4+1)*65 + c],
                               ts[(r4+2)*65 + c], ts[(r4+3)*65 + c]);
        *(float4*)(g_Vtp + (b*DD + ct*64 + c)*MM + mt*64 + r4) = o;
    }
}

// ---------------------------------------------------------------------------
// Fused attention machinery. mma_block: register double-buffered ldmatrix —
// kc+1's fragments are loaded BEFORE kc's prmt+mma sweep, hiding LDS latency.
// ---------------------------------------------------------------------------
#define ASTR 36
#define ESTR 68
#define STAGE_FLOATS (192*ASTR)             // 6912
#define ESM_OFF (2*STAGE_FLOATS)            // 13824
#define ATTN_SMEM_BYTES ((ESM_OFF + 128*ESTR)*4)   // 90112 B

__device__ __forceinline__ void copy_stage(float* buf, const float* Ag, int lda,
                                           const float* Bg, int ldb, int tid) {
#pragma unroll
    for (int ch = 0; ch < 6; ch++) {
        int c = tid + ch*256;               // 0..1535
        int row = c >> 3, k4 = (c & 7)*4;
        if (row < 128)
            CPA(smaddr(buf + row*ASTR + k4), Ag + row*lda + k4);
        else
            CPA(smaddr(buf + row*ASTR + k4), Bg + (row-128)*ldb + k4);
    }
    CP_COMMIT();
}

template<int NKC>
__device__ __forceinline__ void mma_block(const float* As, int astr,
                                          const float* Bs, int bstr,
                                          float4 acc[2][4],
                                          int lane, int wm, int wn) {
    int arow = (lane & 7) + ((lane >> 3) & 1)*8;
    int acol = (lane >> 4)*4;
    int bl   = lane & 15;
    int brow = bl & 7;
    int bcol = (bl >> 3)*4;

    uint32_t ar[2][2][4];      // [buf][mt][slot]
    uint32_t br[2][4][2];      // [buf][nt][slot]
#pragma unroll
    for (int mt = 0; mt < 2; mt++)
        ldsm4(ar[0][mt], As + (wm*32 + mt*16 + arow)*astr + acol);
#pragma unroll
    for (int nt = 0; nt < 4; nt++)
        ldsm2(br[0][nt], Bs + (wn*32 + nt*8 + brow)*bstr + bcol);

#pragma unroll
    for (int kc = 0; kc < NKC; kc++) {
        const int cur = kc & 1, nxt = cur ^ 1;
        if (kc + 1 < NKC) {
            int kk = (kc + 1)*8;
#pragma unroll
            for (int mt = 0; mt < 2; mt++)
                ldsm4(ar[nxt][mt], As + (wm*32 + mt*16 + arow)*astr + kk + acol);
#pragma unroll
            for (int nt = 0; nt < 4; nt++)
                ldsm2(br[nxt][nt], Bs + (wn*32 + nt*8 + brow)*bstr + kk + bcol);
        }
        uint32_t bh[4][2], bL[4][2];
#pragma unroll
        for (int nt = 0; nt < 4; nt++) {
            bh[nt][0] = prmt_rep(br[cur][nt][0], 0x1010u);
            bh[nt][1] = prmt_rep(br[cur][nt][1], 0x1010u);
            bL[nt][0] = prmt_rep(br[cur][nt][0], 0x3232u);
            bL[nt][1] = prmt_rep(br[cur][nt][1], 0x3232u);
        }
#pragma unroll
        for (int nt = 0; nt < 4; nt++)
#pragma unroll
            for (int mt = 0; mt < 2; mt++)
                mma16(acc[mt][nt], ar[cur][mt], bh[nt][0], bh[nt][1]);
#pragma unroll
        for (int nt = 0; nt < 4; nt++)
#pragma unroll
            for (int mt = 0; mt < 2; mt++)
                mma16(acc[mt][nt], ar[cur][mt], bL[nt][0], bL[nt][1]);
    }
}

// ---------------------------------------------------------------------------
// Kernel 4: fused attention. grid = b(4) x mchunk(64 of 64 keys) = 256 CTAs.
// ---------------------------------------------------------------------------
__global__ __launch_bounds__(256, 2) void k_attn() {
    extern __shared__ float sm[];
    __shared__ float srow[128];
    float* Esm = sm + ESM_OFF;
    int tid = threadIdx.x;
    int b  = blockIdx.x >> 6;
    int mb = blockIdx.x & 63;
    const float* Ag = g_Qp + b*NQ*DD;                // [128][256w]
    const float* Bg = g_Kp + (b*MM + mb*64)*DD;      // [64][256w]

    int lane = tid & 31, ww = tid >> 5;
    int lr = lane >> 2, lc = lane & 3;
    int wm = ww & 3, wn = ww >> 2;                   // 4m x 2n warps
    float4 acc[2][4];
#pragma unroll
    for (int i = 0; i < 2; i++)
#pragma unroll
        for (int j = 0; j < 4; j++) acc[i][j] = make_float4(0.f,0.f,0.f,0.f);

    // ---- Phase 1 mainloop ----
    copy_stage(sm, Ag, DD, Bg, DD, tid);
    for (int s = 0; s < 8; s++) {
        if (s < 7)
            copy_stage(sm + ((s+1)&1)*STAGE_FLOATS,
                       Ag + (s+1)*32, DD, Bg + (s+1)*32, DD, tid);
        if (s < 7) asm volatile("cp.async.wait_group 1;");
        else       asm volatile("cp.async.wait_group 0;");
        __syncthreads();
        mma_block<4>(sm + (s&1)*STAGE_FLOATS, ASTR,
                     sm + (s&1)*STAGE_FLOATS + 128*ASTR, ASTR,
                     acc, lane, wm, wn);
        __syncthreads();
    }

    // ---- prefetch Vt panel 0 ----
    {
        const float* Vg = g_Vtp + (b*DD + 0)*MM + mb*64;
#pragma unroll
        for (int ch = 0; ch < 4; ch++) {
            int c = tid + ch*256;
            int row = c >> 4, f4 = (c & 15)*4;
            CPA(smaddr(sm + row*ESTR + f4), Vg + row*MM + f4);
        }
        CP_COMMIT();
    }

    // ---- Phase 1 epilogue: exp, rowsum, pack E into Esm ----
    if (tid < 128) srow[tid] = 0.f;
    __syncthreads();
    float rs[4] = {0.f,0.f,0.f,0.f};
#pragma unroll
    for (int mt = 0; mt < 2; mt++) {
#pragma unroll
        for (int nt = 0; nt < 4; nt++) {
            int row = wm*32 + mt*16 + lr;
            int col = wn*32 + nt*8 + lc*2;
            float4 d = acc[mt][nt];
            float e0 = __expf(d.x), e1 = __expf(d.y);
            float e2 = __expf(d.z), e3 = __expf(d.w);
            rs[mt*2+0] += e0 + e1;
            rs[mt*2+1] += e2 + e3;
            Esm[row*ESTR + col]       = pack_bf(e0);
            Esm[row*ESTR + col + 1]   = pack_bf(e1);
            Esm[(row+8)*ESTR + col]   = pack_bf(e2);
            Esm[(row+8)*ESTR + col+1] = pack_bf(e3);
        }
    }
#pragma unroll
    for (int i = 0; i < 4; i++) {
        rs[i] += __shfl_xor_sync(~0u, rs[i], 1);
        rs[i] += __shfl_xor_sync(~0u, rs[i], 2);
    }
    if (lc == 0) {
#pragma unroll
        for (int i = 0; i < 4; i++)
            atomicAdd(&srow[wm*32 + (i >> 1)*16 + (i & 1)*8 + lr], rs[i]);
    }
    __syncthreads();
    if (tid < 128) atomicAdd(&g_rowsum[b*128 + tid], srow[tid]);

    // ---- Phase 2: 4 cc-blocks of 64, Vt panels double-buffered ----
    for (int cb = 0; cb < 4; cb++) {
        if (cb < 3) {
            const float* Vg = g_Vtp + (b*DD + (cb+1)*64)*MM + mb*64;
            float* pan = sm + ((cb+1)&1)*(64*ESTR);
#pragma unroll
            for (int ch = 0; ch < 4; ch++) {
                int c = tid + ch*256;
                int row = c >> 4, f4 = (c & 15)*4;
                CPA(smaddr(pan + row*ESTR + f4), Vg + row*MM + f4);
            }
            CP_COMMIT();
        }
        if (cb < 3) asm volatile("cp.async.wait_group 1;");
        else        asm volatile("cp.async.wait_group 0;");
        __syncthreads();

        float4 acc2[2][4];
#pragma unroll
        for (int i = 0; i < 2; i++)
#pragma unroll
            for (int j = 0; j < 4; j++) acc2[i][j] = make_float4(0.f,0.f,0.f,0.f);

        mma_block<8>(Esm, ESTR, sm + (cb&1)*(64*ESTR), ESTR,
                     acc2, lane, wm, wn);

        float* Og = g_O + b*NQ*DD + cb*64;
#pragma unroll
        for (int mt = 0; mt < 2; mt++) {
#pragma unroll
            for (int nt = 0; nt < 4; nt++) {
                int row = wm*32 + mt*16 + lr;
                int col = wn*32 + nt*8 + lc*2;
                float4 d = acc2[mt][nt];
                atomicAdd(Og + row*DD + col,       d.x);
                atomicAdd(Og + row*DD + col + 1,   d.y);
                atomicAdd(Og + (row+8)*DD + col,   d.z);
                atomicAdd(Og + (row+8)*DD + col+1, d.w);
            }
        }
        __syncthreads();
    }
}

// ---------------------------------------------------------------------------
// Kernel 5: normalize + scatter to output [B,X,H,W,C], float4.
// ---------------------------------------------------------------------------
__global__ __launch_bounds__(256) void k_out(float* __restrict__ out) {
    int t4 = blockIdx.x*256 + threadIdx.x;
    int t  = t4 * 4;
    int co = t & 31;
    int wo = (t >> 5) & 127;
    int xo = (t >> 15) & 31;
    int b  = t >> 20;
    int n  = xo*4 + ((wo >> 3) & 3);
    int cc = ((wo & 7)*4 + (co >> 3))*8 + (co & 7);
    float inv = __fdividef(1.f, g_rowsum[b*128 + n]);
    float4 v = *(const float4*)(g_O + (b*NQ + n)*DD + cc);
    v.x *= inv; v.y *= inv; v.z *= inv; v.w *= inv;
    *(float4*)(out + t) = v;
}

// ---------------------------------------------------------------------------
extern "C" void kernel_launch(void* const* d_in, const int* in_sizes, int n_in,
                              void* d_out, int out_size) {
    const float* storage = (const float*)d_in[0];
    const float* target  = (const float*)d_in[1];
    const float* w_cross = (const float*)d_in[2];
    const float* b_cross = (const float*)d_in[3];
    const float* w_q     = (const float*)d_in[4];
    const float* b_q     = (const float*)d_in[5];
    float* out = (float*)d_out;

    cudaFuncSetAttribute(k_conv, cudaFuncAttributeMaxDynamicSharedMemorySize,
                         CONV_SMEM_FLOATS * 4);
    cudaFuncSetAttribute(k_attn, cudaFuncAttributeMaxDynamicSharedMemorySize,
                         ATTN_SMEM_BYTES);

    k_q    <<<512,  256>>>(target, w_q, b_q, w_cross);
    k_conv <<<1024, 256, CONV_SMEM_FLOATS*4>>>(storage, b_cross);
    k_vt   <<<1024, 256>>>();
    k_attn <<<256,  256, ATTN_SMEM_BYTES>>>();
    k_out  <<<4096, 256>>>(out);
}